// round 15
// baseline (speedup 1.0000x reference)
#include <cuda_runtime.h>
#include <cuda_fp16.h>
#include <math.h>
#include <stdint.h>

#define B_    4
#define L_    2048
#define HID_  2048
#define H_    16
#define DH_   128
#define QKV_  (3 * HID_)          // 6144
#define PW_   (QKV_ + HID_)       // 8192
#define MTOK_ (B_ * L_)           // 8192
#define EPS_  1e-5f
#define SCALE_ 0.08838834764831845f   // 1/sqrt(128)
#define FULLM 0xffffffffu

// Scratch (allocation-free rule: __device__ globals)
__device__ float  g_proj[(size_t)MTOK_ * PW_];    // 256 MB (f32 proj output)
__device__ __half g_attnh[(size_t)MTOK_ * HID_];  // 32 MB (half, from flash)
__device__ __half g_hidh[(size_t)MTOK_ * HID_];   // 32 MB (half hidden)
__device__ __half g_wqh[(size_t)HID_ * PW_];      // 32 MB (half W_qkvg)
__device__ __half g_woh[(size_t)HID_ * HID_];     // 8 MB  (half W_out)

__device__ __forceinline__ uint32_t h2u(__half2 h) {
    return *(uint32_t*)&h;
}

__device__ __forceinline__ void mma16(float* c, const uint32_t* a, const uint32_t* b) {
    asm volatile(
        "mma.sync.aligned.m16n8k16.row.col.f32.f16.f16.f32 "
        "{%0,%1,%2,%3}, {%4,%5,%6,%7}, {%8,%9}, {%0,%1,%2,%3};\n"
        : "+f"(c[0]), "+f"(c[1]), "+f"(c[2]), "+f"(c[3])
        : "r"(a[0]), "r"(a[1]), "r"(a[2]), "r"(a[3]), "r"(b[0]), "r"(b[1]));
}

// ===========================================================================
// f32 -> f16 convert
// ===========================================================================
__global__ __launch_bounds__(256) void cvt_f16_k(
    const float4* __restrict__ in, uint2* __restrict__ outp, int n4)
{
    const int i = blockIdx.x * 256 + threadIdx.x;
    if (i < n4) {
        float4 v = in[i];
        uint2 o;
        o.x = h2u(__floats2half2_rn(v.x, v.y));
        o.y = h2u(__floats2half2_rn(v.z, v.w));
        outp[i] = o;
    }
}

// ===========================================================================
// fp16 NN GEMM: C[M,N](f32) = A[M,K](half) * B[K,N](half)
// 128 thr/CTA, tile 128x128x32, warp tile 64x64, G2R double buffer, 2 CTA/SM.
// Smem: A row-major half2 words, stride 20; B k-paired half2, stride 136.
// ===========================================================================
#define BM 128
#define BN 128
#define BK 32
#define ASTR16 20                    // u32 per A row (16 data + pad)
#define BSTR16 136                   // u32 per B kp row (128 data + pad)
#define A_ST16 (BM * ASTR16)         // 2560 u32
#define B_ST16 (16 * BSTR16)         // 2176 u32
#define STF16 (A_ST16 + B_ST16)      // 4736 u32
#define GEMM_SMEM (2 * STF16 * 4)    // 37888 bytes

__global__ __launch_bounds__(128, 2) void gemm_h(
    const __half* __restrict__ A, int lda,
    const __half* __restrict__ B, int ldb,
    float* __restrict__ C, int ldc, int K)
{
    extern __shared__ uint32_t smu[];
    const int tid = threadIdx.x;
    const int m0 = blockIdx.y * BM, n0 = blockIdx.x * BN;
    const int warp = tid >> 5, lane = tid & 31;
    const int wm = (warp >> 1) * 64;
    const int wn = (warp & 1) * 64;
    const int lr = lane >> 2, lc = lane & 3;

    // A loader: thread = one row (tid 0..127), 4 x uint4 (64B = full 32-half row)
    // B loader: kp = tid>>3 (0..15), nq = tid&7; 4 chunks of 4 cols at nq*4+32c
    const int kp = tid >> 3, nq = tid & 7;

    uint4 st_a[4];
    uint2 st_b[8];

#define G2R_A(kt)                                                            \
    {                                                                        \
        const uint4* ag =                                                    \
            (const uint4*)(A + (size_t)(m0 + tid) * lda + (kt) * BK);        \
        _Pragma("unroll")                                                    \
        for (int c = 0; c < 4; c++) st_a[c] = ag[c];                         \
    }
#define R2S_A(pp)                                                            \
    {                                                                        \
        uint32_t* as = smu + (pp) * STF16;                                   \
        _Pragma("unroll")                                                    \
        for (int c = 0; c < 4; c++)                                          \
            *(uint4*)(as + tid * ASTR16 + c * 4) = st_a[c];                  \
    }
#define G2R_B(kt)                                                            \
    {                                                                        \
        const __half* b0p =                                                  \
            B + (size_t)((kt) * BK + 2 * kp) * ldb + n0 + nq * 4;            \
        _Pragma("unroll")                                                    \
        for (int c = 0; c < 4; c++) {                                        \
            st_b[2 * c]     = *(const uint2*)(b0p + c * 32);                 \
            st_b[2 * c + 1] = *(const uint2*)(b0p + ldb + c * 32);           \
        }                                                                    \
    }
#define R2S_B(pp)                                                            \
    {                                                                        \
        uint32_t* bs = smu + (pp) * STF16 + A_ST16;                          \
        _Pragma("unroll")                                                    \
        for (int c = 0; c < 4; c++) {                                        \
            uint4 o;                                                         \
            o.x = __byte_perm(st_b[2*c].x, st_b[2*c+1].x, 0x5410);           \
            o.y = __byte_perm(st_b[2*c].x, st_b[2*c+1].x, 0x7632);           \
            o.z = __byte_perm(st_b[2*c].y, st_b[2*c+1].y, 0x5410);           \
            o.w = __byte_perm(st_b[2*c].y, st_b[2*c+1].y, 0x7632);           \
            *(uint4*)(bs + kp * BSTR16 + nq * 4 + 32 * c) = o;               \
        }                                                                    \
    }

    float acc[4][8][4];
#pragma unroll
    for (int mt = 0; mt < 4; mt++)
#pragma unroll
        for (int nt = 0; nt < 8; nt++)
#pragma unroll
            for (int e = 0; e < 4; e++) acc[mt][nt][e] = 0.f;

#define COMP(pp, ks)                                                         \
    {                                                                        \
        const uint32_t* As_ = smu + (pp) * STF16;                            \
        const uint32_t* Bs_ = As_ + A_ST16;                                  \
        const int kb = (ks) * 8;                                             \
        uint32_t af[4][4];                                                   \
        _Pragma("unroll")                                                    \
        for (int mt = 0; mt < 4; mt++) {                                     \
            const int r = wm + mt * 16 + lr;                                 \
            af[mt][0] = As_[r * ASTR16 + kb + lc];                           \
            af[mt][1] = As_[(r + 8) * ASTR16 + kb + lc];                     \
            af[mt][2] = As_[r * ASTR16 + kb + lc + 4];                       \
            af[mt][3] = As_[(r + 8) * ASTR16 + kb + lc + 4];                 \
        }                                                                    \
        uint32_t bf[8][2];                                                   \
        _Pragma("unroll")                                                    \
        for (int nt = 0; nt < 8; nt++) {                                     \
            const int n = wn + nt * 8 + lr;                                  \
            bf[nt][0] = Bs_[(kb + lc) * BSTR16 + n];                         \
            bf[nt][1] = Bs_[(kb + lc + 4) * BSTR16 + n];                     \
        }                                                                    \
        _Pragma("unroll")                                                    \
        for (int mt = 0; mt < 4; mt++)                                       \
            _Pragma("unroll")                                                \
            for (int nt = 0; nt < 8; nt++)                                   \
                mma16(acc[mt][nt], af[mt], bf[nt]);                          \
    }

    G2R_A(0); R2S_A(0);
    G2R_B(0); R2S_B(0);
    __syncthreads();

    const int T = K >> 5;
    for (int t = 0; t < T; t++) {
        const int p = t & 1;
        const bool nx = (t + 1 < T);
        if (nx) G2R_A(t + 1);
        COMP(p, 0);
        if (nx) { R2S_A(p ^ 1); G2R_B(t + 1); }
        COMP(p, 1);
        if (nx) R2S_B(p ^ 1);
        __syncthreads();
    }

#pragma unroll
    for (int mt = 0; mt < 4; mt++)
#pragma unroll
        for (int nt = 0; nt < 8; nt++) {
            const int r = m0 + wm + mt * 16 + lr;
            const int c = n0 + wn + nt * 8 + lc * 2;
            *(float2*)(C + (size_t)r * ldc + c) =
                make_float2(acc[mt][nt][0], acc[mt][nt][1]);
            *(float2*)(C + (size_t)(r + 8) * ldc + c) =
                make_float2(acc[mt][nt][2], acc[mt][nt][3]);
        }
#undef G2R_A
#undef R2S_A
#undef G2R_B
#undef R2S_B
#undef COMP
}

// ===========================================================================
// Flash attention fp16 (causal, online softmax) + sigmoid gate.
// Q/K smem: row-major half2 words stride 68. V smem: k-paired half2 stride 136.
// P lives in registers (packed half2 pairs align with fp16 A-fragments).
// ===========================================================================
#define QST 68
#define VST 136
#define QSZ16 (128 * QST)           // 8704 u32
#define VSZ16 (64 * VST)            // 8704 u32
#define FLASH_SMEM ((2 * QSZ16 + VSZ16) * 4)   // 104448 bytes

__global__ __launch_bounds__(256, 1) void flash_h(
    const float* __restrict__ proj, __half* __restrict__ attnh)
{
    extern __shared__ uint32_t smu[];
    uint32_t* Qs = smu;
    uint32_t* Ks = smu + QSZ16;
    uint32_t* Vs = smu + 2 * QSZ16;

    const int it = blockIdx.x, bh = blockIdx.y;
    const int b = bh >> 4, h = bh & 15;
    const size_t base = (size_t)b * L_ * PW_;
    const float* Qp = proj + base + (size_t)h * DH_;
    const float* Kp = proj + base + (size_t)(H_ + h) * DH_;
    const float* Vp = proj + base + (size_t)(2 * H_ + h) * DH_;
    const float* Gp = proj + base + QKV_ + (size_t)h * DH_;
    __half* Op = attnh + (size_t)b * L_ * HID_ + (size_t)h * DH_;

    const int tid = threadIdx.x, warp = tid >> 5, lane = tid & 31;
    const int lr = lane >> 2, lc = lane & 3;
    const int wm = warp * 16;
    const int i0 = it * 128;

    // --- Q load: 256 tasks (row, halfchunk); lane covers 2 f32 -> 1 half2 ---
#pragma unroll 4
    for (int i = 0; i < 32; i++) {
        const int task = warp * 32 + i;
        const int row = task >> 1, ch = task & 1;
        float2 v = *(const float2*)(Qp + (size_t)(i0 + row) * PW_ + ch * 64 + 2 * lane);
        Qs[row * QST + ch * 32 + lane] =
            h2u(__floats2half2_rn(v.x * SCALE_, v.y * SCALE_));
    }

    float m0v = -1e30f, m1v = -1e30f, l0 = 0.f, l1 = 0.f;
    float oacc[16][4];
#pragma unroll
    for (int nt = 0; nt < 16; nt++)
#pragma unroll
        for (int e = 0; e < 4; e++) oacc[nt][e] = 0.f;

    const int r0g = i0 + wm + lr, r1g = r0g + 8;

    for (int jt = 0; jt <= it; ++jt) {
        const int j0 = jt * 128;
        // --- K load (row-major half2) ---
#pragma unroll 4
        for (int i = 0; i < 32; i++) {
            const int task = warp * 32 + i;
            const int row = task >> 1, ch = task & 1;
            float2 v = *(const float2*)(Kp + (size_t)(j0 + row) * PW_ + ch * 64 + 2 * lane);
            Ks[row * QST + ch * 32 + lane] = h2u(__floats2half2_rn(v.x, v.y));
        }
        // --- V load (k-paired half2: word = {V[2kp][d], V[2kp+1][d]}) ---
#pragma unroll 4
        for (int i = 0; i < 32; i++) {
            const int task = warp * 32 + i;
            const int kpv = task >> 2, dc = task & 3;
            const int d = dc * 32 + lane;
            float f0 = Vp[(size_t)(j0 + 2 * kpv) * PW_ + d];
            float f1 = Vp[(size_t)(j0 + 2 * kpv + 1) * PW_ + d];
            Vs[kpv * VST + d] = h2u(__floats2half2_rn(f0, f1));
        }
        __syncthreads();

        // --- S = Q @ K^T : 8 ksteps of 16, 16 n-tiles ---
        float sacc[16][4];
#pragma unroll
        for (int nt = 0; nt < 16; nt++)
#pragma unroll
            for (int e = 0; e < 4; e++) sacc[nt][e] = 0.f;

#pragma unroll
        for (int ks = 0; ks < 8; ks++) {
            const int kb = ks * 8;
            uint32_t a[4];
            a[0] = Qs[(wm + lr) * QST + kb + lc];
            a[1] = Qs[(wm + lr + 8) * QST + kb + lc];
            a[2] = Qs[(wm + lr) * QST + kb + lc + 4];
            a[3] = Qs[(wm + lr + 8) * QST + kb + lc + 4];
#pragma unroll
            for (int nt = 0; nt < 16; nt++) {
                uint32_t bf[2];
                bf[0] = Ks[(nt * 8 + lr) * QST + kb + lc];
                bf[1] = Ks[(nt * 8 + lr) * QST + kb + lc + 4];
                mma16(sacc[nt], a, bf);
            }
        }

        // causal mask on the diagonal tile
        if (jt == it) {
#pragma unroll
            for (int nt = 0; nt < 16; nt++) {
                const int c0 = j0 + nt * 8 + 2 * lc;
                if (c0 > r0g)     sacc[nt][0] = -1e30f;
                if (c0 + 1 > r0g) sacc[nt][1] = -1e30f;
                if (c0 > r1g)     sacc[nt][2] = -1e30f;
                if (c0 + 1 > r1g) sacc[nt][3] = -1e30f;
            }
        }

        // online softmax stats (quad reduce)
        float tm0 = -1e30f, tm1 = -1e30f;
#pragma unroll
        for (int nt = 0; nt < 16; nt++) {
            tm0 = fmaxf(tm0, fmaxf(sacc[nt][0], sacc[nt][1]));
            tm1 = fmaxf(tm1, fmaxf(sacc[nt][2], sacc[nt][3]));
        }
        tm0 = fmaxf(tm0, __shfl_xor_sync(FULLM, tm0, 1));
        tm0 = fmaxf(tm0, __shfl_xor_sync(FULLM, tm0, 2));
        tm1 = fmaxf(tm1, __shfl_xor_sync(FULLM, tm1, 1));
        tm1 = fmaxf(tm1, __shfl_xor_sync(FULLM, tm1, 2));

        const float mn0 = fmaxf(m0v, tm0), mn1 = fmaxf(m1v, tm1);
        const float sc0 = __expf(m0v - mn0), sc1 = __expf(m1v - mn1);
        m0v = mn0; m1v = mn1;

        uint32_t pk[16][2];
        float rs0 = 0.f, rs1 = 0.f;
#pragma unroll
        for (int nt = 0; nt < 16; nt++) {
            float p0 = __expf(sacc[nt][0] - mn0);
            float p1 = __expf(sacc[nt][1] - mn0);
            float p2 = __expf(sacc[nt][2] - mn1);
            float p3 = __expf(sacc[nt][3] - mn1);
            rs0 += p0 + p1; rs1 += p2 + p3;
            pk[nt][0] = h2u(__floats2half2_rn(p0, p1));
            pk[nt][1] = h2u(__floats2half2_rn(p2, p3));
            oacc[nt][0] *= sc0; oacc[nt][1] *= sc0;
            oacc[nt][2] *= sc1; oacc[nt][3] *= sc1;
        }
        rs0 += __shfl_xor_sync(FULLM, rs0, 1);
        rs0 += __shfl_xor_sync(FULLM, rs0, 2);
        rs1 += __shfl_xor_sync(FULLM, rs1, 1);
        rs1 += __shfl_xor_sync(FULLM, rs1, 2);
        l0 = l0 * sc0 + rs0;
        l1 = l1 * sc1 + rs1;

        // --- O += P @ V : A-frags straight from pk registers ---
#pragma unroll
        for (int ks = 0; ks < 8; ks++) {
            uint32_t a[4];
            a[0] = pk[2 * ks][0];
            a[1] = pk[2 * ks][1];
            a[2] = pk[2 * ks + 1][0];
            a[3] = pk[2 * ks + 1][1];
            const int kb = ks * 8;
#pragma unroll
            for (int nt = 0; nt < 16; nt++) {
                uint32_t bf[2];
                bf[0] = Vs[(kb + lc) * VST + nt * 8 + lr];
                bf[1] = Vs[(kb + lc + 4) * VST + nt * 8 + lr];
                mma16(oacc[nt], a, bf);
            }
        }
        __syncthreads();
    }

    // epilogue: normalize, sigmoid gate, store half
    const float inv0 = 1.f / l0, inv1 = 1.f / l1;
#pragma unroll
    for (int nt = 0; nt < 16; nt++) {
        const int c = nt * 8 + 2 * lc;
        const float2 g0 = *(const float2*)(Gp + (size_t)r0g * PW_ + c);
        const float2 g1 = *(const float2*)(Gp + (size_t)r1g * PW_ + c);
        float o0 = oacc[nt][0] * inv0 * (1.f / (1.f + __expf(-g0.x)));
        float o1 = oacc[nt][1] * inv0 * (1.f / (1.f + __expf(-g0.y)));
        float o2 = oacc[nt][2] * inv1 * (1.f / (1.f + __expf(-g1.x)));
        float o3 = oacc[nt][3] * inv1 * (1.f / (1.f + __expf(-g1.y)));
        *(uint32_t*)(Op + (size_t)r0g * HID_ + c) = h2u(__floats2half2_rn(o0, o1));
        *(uint32_t*)(Op + (size_t)r1g * HID_ + c) = h2u(__floats2half2_rn(o2, o3));
    }
}

// ===========================================================================
// RMSNorm + RoPE in place on q (heads 0..15) and k (heads 16..31) of g_proj.
// ===========================================================================
__global__ __launch_bounds__(256) void norm_rope_kernel(float* __restrict__ proj)
{
    const int warp = blockIdx.x * 8 + (threadIdx.x >> 5);
    const int lane = threadIdx.x & 31;
    const int head2 = warp & 31;
    const int tok = warp >> 5;
    const int pos = tok & (L_ - 1);

    float* x = proj + (size_t)tok * PW_ + (size_t)head2 * DH_;
    float v0 = x[lane];
    float v1 = x[lane + 32];
    float v2 = x[lane + 64];
    float v3 = x[lane + 96];

    float ss = v0 * v0 + v1 * v1 + v2 * v2 + v3 * v3;
#pragma unroll
    for (int o = 16; o; o >>= 1) ss += __shfl_xor_sync(FULLM, ss, o);
    const float r = rsqrtf(ss * (1.0f / DH_) + EPS_);
    v0 *= r; v1 *= r; v2 *= r; v3 *= r;

    const float kf = 9.210340371976184f / 64.0f;
    const float fpos = (float)pos;
    const float a0 = fpos * __expf(-kf * (float)lane);
    const float a1 = fpos * __expf(-kf * (float)(lane + 32));
    float c0, s0, c1, s1;
    sincosf(a0, &s0, &c0);
    sincosf(a1, &s1, &c1);

    x[lane]      = v0 * c0 - v2 * s0;
    x[lane + 64] = v0 * s0 + v2 * c0;
    x[lane + 32] = v1 * c1 - v3 * s1;
    x[lane + 96] = v1 * s1 + v3 * c1;
}

// ===========================================================================
extern "C" void kernel_launch(void* const* d_in, const int* in_sizes, int n_in,
                              void* d_out, int out_size)
{
    const float* hidden = (const float*)d_in[0];   // [B,L,HID]
    const float* Wqkvg  = (const float*)d_in[1];   // [HID, PW]
    const float* Wout   = (const float*)d_in[2];   // [HID, HID]
    float* out = (float*)d_out;                    // [B,L,HID]

    float* proj;
    __half *attnh, *hidh, *wqh, *woh;
    cudaGetSymbolAddress((void**)&proj,  g_proj);
    cudaGetSymbolAddress((void**)&attnh, g_attnh);
    cudaGetSymbolAddress((void**)&hidh,  g_hidh);
    cudaGetSymbolAddress((void**)&wqh,   g_wqh);
    cudaGetSymbolAddress((void**)&woh,   g_woh);

    cudaFuncSetAttribute(gemm_h,
                         cudaFuncAttributeMaxDynamicSharedMemorySize, GEMM_SMEM);
    cudaFuncSetAttribute(flash_h,
                         cudaFuncAttributeMaxDynamicSharedMemorySize, FLASH_SMEM);

    // 0) convert inputs to fp16
    {
        const int n4h = MTOK_ * HID_ / 4;
        cvt_f16_k<<<(n4h + 255) / 256, 256>>>((const float4*)hidden,
                                              (uint2*)hidh, n4h);
        const int n4q = HID_ * PW_ / 4;
        cvt_f16_k<<<(n4q + 255) / 256, 256>>>((const float4*)Wqkvg,
                                              (uint2*)wqh, n4q);
        const int n4o = HID_ * HID_ / 4;
        cvt_f16_k<<<(n4o + 255) / 256, 256>>>((const float4*)Wout,
                                              (uint2*)woh, n4o);
    }

    // 1) proj = hidden @ W_qkvg   (fp16 mma, f32 accum)
    gemm_h<<<dim3(PW_ / BN, MTOK_ / BM), 128, GEMM_SMEM>>>(
        hidh, HID_, wqh, PW_, proj, PW_, HID_);

    // 2) RMSNorm + RoPE on q,k (f32, in place)
    norm_rope_kernel<<<(MTOK_ * 2 * H_) / 8, 256>>>(proj);

    // 3) fused flash attention + gate (fp16 mma; writes half attn)
    flash_h<<<dim3(L_ / 128, B_ * H_), 256, FLASH_SMEM>>>(proj, attnh);

    // 4) out = attn @ W_out
    gemm_h<<<dim3(HID_ / BN, MTOK_ / BM), 128, GEMM_SMEM>>>(
        attnh, HID_, woh, HID_, out, HID_, HID_);
}

// round 16
// speedup vs baseline: 1.4735x; 1.4735x over previous
#include <cuda_runtime.h>
#include <cuda_fp16.h>
#include <math.h>
#include <stdint.h>

#define B_    4
#define L_    2048
#define HID_  2048
#define H_    16
#define DH_   128
#define QKV_  (3 * HID_)          // 6144
#define PW_   (QKV_ + HID_)       // 8192
#define MTOK_ (B_ * L_)           // 8192
#define EPS_  1e-5f
#define SCALE_ 0.08838834764831845f   // 1/sqrt(128)
#define FULLM 0xffffffffu

// Scratch (allocation-free rule: __device__ globals)
__device__ float  g_proj[(size_t)MTOK_ * PW_];    // 256 MB (f32 proj output)
__device__ __half g_attnh[(size_t)MTOK_ * HID_];  // 32 MB (half, from flash)
__device__ __half g_hidh[(size_t)MTOK_ * HID_];   // 32 MB (half hidden)
__device__ __half g_wqh[(size_t)HID_ * PW_];      // 32 MB (half W_qkvg)
__device__ __half g_woh[(size_t)HID_ * HID_];     // 8 MB  (half W_out)

__device__ __forceinline__ uint32_t h2u(__half2 h) {
    return *(uint32_t*)&h;
}

__device__ __forceinline__ void mma16(float* c, const uint32_t* a, const uint32_t* b) {
    asm volatile(
        "mma.sync.aligned.m16n8k16.row.col.f32.f16.f16.f32 "
        "{%0,%1,%2,%3}, {%4,%5,%6,%7}, {%8,%9}, {%0,%1,%2,%3};\n"
        : "+f"(c[0]), "+f"(c[1]), "+f"(c[2]), "+f"(c[3])
        : "r"(a[0]), "r"(a[1]), "r"(a[2]), "r"(a[3]), "r"(b[0]), "r"(b[1]));
}

__device__ __forceinline__ void ldsm4(uint32_t* r, uint32_t addr) {
    asm volatile(
        "ldmatrix.sync.aligned.m8n8.x4.shared.b16 {%0,%1,%2,%3}, [%4];"
        : "=r"(r[0]), "=r"(r[1]), "=r"(r[2]), "=r"(r[3]) : "r"(addr));
}

__device__ __forceinline__ void ldsm4t(uint32_t* r, uint32_t addr) {
    asm volatile(
        "ldmatrix.sync.aligned.m8n8.x4.trans.shared.b16 {%0,%1,%2,%3}, [%4];"
        : "=r"(r[0]), "=r"(r[1]), "=r"(r[2]), "=r"(r[3]) : "r"(addr));
}

// ===========================================================================
// f32 -> f16 convert
// ===========================================================================
__global__ __launch_bounds__(256) void cvt_f16_k(
    const float4* __restrict__ in, uint2* __restrict__ outp, int n4)
{
    const int i = blockIdx.x * 256 + threadIdx.x;
    if (i < n4) {
        float4 v = in[i];
        uint2 o;
        o.x = h2u(__floats2half2_rn(v.x, v.y));
        o.y = h2u(__floats2half2_rn(v.z, v.w));
        outp[i] = o;
    }
}

// ===========================================================================
// fp16 NN GEMM via ldmatrix: C[M,N](f32) = A[M,K](half) * B[K,N](half)
// 128 thr/CTA, tile 128x128x32, warp tile 64x64, G2R double buffer, 2 CTA/SM.
// A smem: row-major halves, row stride 20 u32 (LDSM-conflict-free).
// B smem: row-major [k][n] halves, row stride 68 u32 (LDSM-conflict-free).
// ===========================================================================
#define BM 128
#define BN 128
#define BK 32
#define ASTRu 20                     // u32 per A row (16 data + 4 pad)
#define BSTRu 68                     // u32 per B row (64 data + 4 pad)
#define A_STu (BM * ASTRu)           // 2560 u32
#define B_STu (BK * BSTRu)           // 2176 u32
#define STFu (A_STu + B_STu)         // 4736 u32
#define GEMM_SMEM (2 * STFu * 4)     // 37888 bytes

__global__ __launch_bounds__(128, 2) void gemm_h(
    const __half* __restrict__ A, int lda,
    const __half* __restrict__ B, int ldb,
    float* __restrict__ C, int ldc, int K)
{
    extern __shared__ uint32_t smu[];
    const int tid = threadIdx.x;
    const int m0 = blockIdx.y * BM, n0 = blockIdx.x * BN;
    const int warp = tid >> 5, lane = tid & 31;
    const int wm = (warp >> 1) * 64;
    const int wn = (warp & 1) * 64;
    const int lr = lane >> 2, lc = lane & 3;

    const uint32_t sb = (uint32_t)__cvta_generic_to_shared(smu);

    // ldmatrix per-lane byte offsets
    // A x4: lanes 0-15 -> rows 0..15 (k-lo), lanes 16-31 -> rows 0..15 (k-hi)
    const uint32_t aoff = (uint32_t)((lane & 15) * (ASTRu * 4) + (lane >> 4) * 16);
    // B x4.trans: row = (lane&7) + ((lane>>3)&1)*8, col halves += (lane>>4)*8
    const uint32_t boff = (uint32_t)(((lane & 7) + ((lane >> 3) & 1) * 8) * (BSTRu * 4)
                                     + ((lane >> 4) * 8) * 2);

    const int br = tid >> 2, bq = tid & 3;
    uint4 st_a[4], st_b[4];

#define G2R_A(kt)                                                            \
    {                                                                        \
        const uint4* ag =                                                    \
            (const uint4*)(A + (size_t)(m0 + tid) * lda + (kt) * BK);        \
        _Pragma("unroll")                                                    \
        for (int c = 0; c < 4; c++) st_a[c] = ag[c];                         \
    }
#define R2S_A(pp)                                                            \
    {                                                                        \
        uint32_t* as = smu + (pp) * STFu + tid * ASTRu;                      \
        _Pragma("unroll")                                                    \
        for (int c = 0; c < 4; c++) *(uint4*)(as + c * 4) = st_a[c];         \
    }
#define G2R_B(kt)                                                            \
    {                                                                        \
        const __half* bg = B + (size_t)((kt) * BK + br) * ldb + n0;          \
        _Pragma("unroll")                                                    \
        for (int c = 0; c < 4; c++)                                          \
            st_b[c] = *(const uint4*)(bg + (c * 4 + bq) * 8);                \
    }
#define R2S_B(pp)                                                            \
    {                                                                        \
        uint32_t* bs = smu + (pp) * STFu + A_STu + br * BSTRu;               \
        _Pragma("unroll")                                                    \
        for (int c = 0; c < 4; c++)                                          \
            *(uint4*)(bs + (c * 4 + bq) * 4) = st_b[c];                      \
    }

    float acc[4][8][4];
#pragma unroll
    for (int mt = 0; mt < 4; mt++)
#pragma unroll
        for (int nt = 0; nt < 8; nt++)
#pragma unroll
            for (int e = 0; e < 4; e++) acc[mt][nt][e] = 0.f;

#define COMP(pp, ks)                                                         \
    {                                                                        \
        const uint32_t ab = sb + (pp) * (STFu * 4);                          \
        const uint32_t bb = ab + A_STu * 4;                                  \
        uint32_t af[4][4];                                                   \
        _Pragma("unroll")                                                    \
        for (int mt = 0; mt < 4; mt++)                                       \
            ldsm4(af[mt],                                                    \
                  ab + (wm + mt * 16) * (ASTRu * 4) + aoff + (ks) * 32);     \
        uint32_t bf[4][4];                                                   \
        _Pragma("unroll")                                                    \
        for (int nt2 = 0; nt2 < 4; nt2++)                                    \
            ldsm4t(bf[nt2],                                                  \
                   bb + (ks) * 16 * (BSTRu * 4) + boff                       \
                      + (wn + nt2 * 16) * 2);                                \
        _Pragma("unroll")                                                    \
        for (int mt = 0; mt < 4; mt++)                                       \
            _Pragma("unroll")                                                \
            for (int nt2 = 0; nt2 < 4; nt2++) {                              \
                mma16(acc[mt][2 * nt2], af[mt], &bf[nt2][0]);                \
                mma16(acc[mt][2 * nt2 + 1], af[mt], &bf[nt2][2]);            \
            }                                                                \
    }

    G2R_A(0); R2S_A(0);
    G2R_B(0); R2S_B(0);
    __syncthreads();

    const int T = K >> 5;
    for (int t = 0; t < T; t++) {
        const int p = t & 1;
        const bool nx = (t + 1 < T);
        if (nx) G2R_A(t + 1);
        COMP(p, 0);
        if (nx) { R2S_A(p ^ 1); G2R_B(t + 1); }
        COMP(p, 1);
        if (nx) R2S_B(p ^ 1);
        __syncthreads();
    }

#pragma unroll
    for (int mt = 0; mt < 4; mt++)
#pragma unroll
        for (int nt = 0; nt < 8; nt++) {
            const int r = m0 + wm + mt * 16 + lr;
            const int c = n0 + wn + nt * 8 + lc * 2;
            *(float2*)(C + (size_t)r * ldc + c) =
                make_float2(acc[mt][nt][0], acc[mt][nt][1]);
            *(float2*)(C + (size_t)(r + 8) * ldc + c) =
                make_float2(acc[mt][nt][2], acc[mt][nt][3]);
        }
#undef G2R_A
#undef R2S_A
#undef G2R_B
#undef R2S_B
#undef COMP
}

// ===========================================================================
// Flash attention fp16 (causal, online softmax) + sigmoid gate.
// Q/K smem: row-major half2 words stride 68. V smem: k-paired half2 stride 136.
// P lives in registers (packed half2 pairs align with fp16 A-fragments).
// ===========================================================================
#define QST 68
#define VST 136
#define QSZ16 (128 * QST)           // 8704 u32
#define VSZ16 (64 * VST)            // 8704 u32
#define FLASH_SMEM ((2 * QSZ16 + VSZ16) * 4)   // 104448 bytes

__global__ __launch_bounds__(256, 1) void flash_h(
    const float* __restrict__ proj, __half* __restrict__ attnh)
{
    extern __shared__ uint32_t smu[];
    uint32_t* Qs = smu;
    uint32_t* Ks = smu + QSZ16;
    uint32_t* Vs = smu + 2 * QSZ16;

    const int it = blockIdx.x, bh = blockIdx.y;
    const int b = bh >> 4, h = bh & 15;
    const size_t base = (size_t)b * L_ * PW_;
    const float* Qp = proj + base + (size_t)h * DH_;
    const float* Kp = proj + base + (size_t)(H_ + h) * DH_;
    const float* Vp = proj + base + (size_t)(2 * H_ + h) * DH_;
    const float* Gp = proj + base + QKV_ + (size_t)h * DH_;
    __half* Op = attnh + (size_t)b * L_ * HID_ + (size_t)h * DH_;

    const int tid = threadIdx.x, warp = tid >> 5, lane = tid & 31;
    const int lr = lane >> 2, lc = lane & 3;
    const int wm = warp * 16;
    const int i0 = it * 128;

#pragma unroll 4
    for (int i = 0; i < 32; i++) {
        const int task = warp * 32 + i;
        const int row = task >> 1, ch = task & 1;
        float2 v = *(const float2*)(Qp + (size_t)(i0 + row) * PW_ + ch * 64 + 2 * lane);
        Qs[row * QST + ch * 32 + lane] =
            h2u(__floats2half2_rn(v.x * SCALE_, v.y * SCALE_));
    }

    float m0v = -1e30f, m1v = -1e30f, l0 = 0.f, l1 = 0.f;
    float oacc[16][4];
#pragma unroll
    for (int nt = 0; nt < 16; nt++)
#pragma unroll
        for (int e = 0; e < 4; e++) oacc[nt][e] = 0.f;

    const int r0g = i0 + wm + lr, r1g = r0g + 8;

    for (int jt = 0; jt <= it; ++jt) {
        const int j0 = jt * 128;
#pragma unroll 4
        for (int i = 0; i < 32; i++) {
            const int task = warp * 32 + i;
            const int row = task >> 1, ch = task & 1;
            float2 v = *(const float2*)(Kp + (size_t)(j0 + row) * PW_ + ch * 64 + 2 * lane);
            Ks[row * QST + ch * 32 + lane] = h2u(__floats2half2_rn(v.x, v.y));
        }
#pragma unroll 4
        for (int i = 0; i < 32; i++) {
            const int task = warp * 32 + i;
            const int kpv = task >> 2, dc = task & 3;
            const int d = dc * 32 + lane;
            float f0 = Vp[(size_t)(j0 + 2 * kpv) * PW_ + d];
            float f1 = Vp[(size_t)(j0 + 2 * kpv + 1) * PW_ + d];
            Vs[kpv * VST + d] = h2u(__floats2half2_rn(f0, f1));
        }
        __syncthreads();

        float sacc[16][4];
#pragma unroll
        for (int nt = 0; nt < 16; nt++)
#pragma unroll
            for (int e = 0; e < 4; e++) sacc[nt][e] = 0.f;

#pragma unroll
        for (int ks = 0; ks < 8; ks++) {
            const int kb = ks * 8;
            uint32_t a[4];
            a[0] = Qs[(wm + lr) * QST + kb + lc];
            a[1] = Qs[(wm + lr + 8) * QST + kb + lc];
            a[2] = Qs[(wm + lr) * QST + kb + lc + 4];
            a[3] = Qs[(wm + lr + 8) * QST + kb + lc + 4];
#pragma unroll
            for (int nt = 0; nt < 16; nt++) {
                uint32_t bf[2];
                bf[0] = Ks[(nt * 8 + lr) * QST + kb + lc];
                bf[1] = Ks[(nt * 8 + lr) * QST + kb + lc + 4];
                mma16(sacc[nt], a, bf);
            }
        }

        if (jt == it) {
#pragma unroll
            for (int nt = 0; nt < 16; nt++) {
                const int c0 = j0 + nt * 8 + 2 * lc;
                if (c0 > r0g)     sacc[nt][0] = -1e30f;
                if (c0 + 1 > r0g) sacc[nt][1] = -1e30f;
                if (c0 > r1g)     sacc[nt][2] = -1e30f;
                if (c0 + 1 > r1g) sacc[nt][3] = -1e30f;
            }
        }

        float tm0 = -1e30f, tm1 = -1e30f;
#pragma unroll
        for (int nt = 0; nt < 16; nt++) {
            tm0 = fmaxf(tm0, fmaxf(sacc[nt][0], sacc[nt][1]));
            tm1 = fmaxf(tm1, fmaxf(sacc[nt][2], sacc[nt][3]));
        }
        tm0 = fmaxf(tm0, __shfl_xor_sync(FULLM, tm0, 1));
        tm0 = fmaxf(tm0, __shfl_xor_sync(FULLM, tm0, 2));
        tm1 = fmaxf(tm1, __shfl_xor_sync(FULLM, tm1, 1));
        tm1 = fmaxf(tm1, __shfl_xor_sync(FULLM, tm1, 2));

        const float mn0 = fmaxf(m0v, tm0), mn1 = fmaxf(m1v, tm1);
        const float sc0 = __expf(m0v - mn0), sc1 = __expf(m1v - mn1);
        m0v = mn0; m1v = mn1;

        uint32_t pk[16][2];
        float rs0 = 0.f, rs1 = 0.f;
#pragma unroll
        for (int nt = 0; nt < 16; nt++) {
            float p0 = __expf(sacc[nt][0] - mn0);
            float p1 = __expf(sacc[nt][1] - mn0);
            float p2 = __expf(sacc[nt][2] - mn1);
            float p3 = __expf(sacc[nt][3] - mn1);
            rs0 += p0 + p1; rs1 += p2 + p3;
            pk[nt][0] = h2u(__floats2half2_rn(p0, p1));
            pk[nt][1] = h2u(__floats2half2_rn(p2, p3));
            oacc[nt][0] *= sc0; oacc[nt][1] *= sc0;
            oacc[nt][2] *= sc1; oacc[nt][3] *= sc1;
        }
        rs0 += __shfl_xor_sync(FULLM, rs0, 1);
        rs0 += __shfl_xor_sync(FULLM, rs0, 2);
        rs1 += __shfl_xor_sync(FULLM, rs1, 1);
        rs1 += __shfl_xor_sync(FULLM, rs1, 2);
        l0 = l0 * sc0 + rs0;
        l1 = l1 * sc1 + rs1;

#pragma unroll
        for (int ks = 0; ks < 8; ks++) {
            uint32_t a[4];
            a[0] = pk[2 * ks][0];
            a[1] = pk[2 * ks][1];
            a[2] = pk[2 * ks + 1][0];
            a[3] = pk[2 * ks + 1][1];
            const int kb = ks * 8;
#pragma unroll
            for (int nt = 0; nt < 16; nt++) {
                uint32_t bf[2];
                bf[0] = Vs[(kb + lc) * VST + nt * 8 + lr];
                bf[1] = Vs[(kb + lc + 4) * VST + nt * 8 + lr];
                mma16(oacc[nt], a, bf);
            }
        }
        __syncthreads();
    }

    const float inv0 = 1.f / l0, inv1 = 1.f / l1;
#pragma unroll
    for (int nt = 0; nt < 16; nt++) {
        const int c = nt * 8 + 2 * lc;
        const float2 g0 = *(const float2*)(Gp + (size_t)r0g * PW_ + c);
        const float2 g1 = *(const float2*)(Gp + (size_t)r1g * PW_ + c);
        float o0 = oacc[nt][0] * inv0 * (1.f / (1.f + __expf(-g0.x)));
        float o1 = oacc[nt][1] * inv0 * (1.f / (1.f + __expf(-g0.y)));
        float o2 = oacc[nt][2] * inv1 * (1.f / (1.f + __expf(-g1.x)));
        float o3 = oacc[nt][3] * inv1 * (1.f / (1.f + __expf(-g1.y)));
        *(uint32_t*)(Op + (size_t)r0g * HID_ + c) = h2u(__floats2half2_rn(o0, o1));
        *(uint32_t*)(Op + (size_t)r1g * HID_ + c) = h2u(__floats2half2_rn(o2, o3));
    }
}

// ===========================================================================
// RMSNorm + RoPE in place on q (heads 0..15) and k (heads 16..31) of g_proj.
// ===========================================================================
__global__ __launch_bounds__(256) void norm_rope_kernel(float* __restrict__ proj)
{
    const int warp = blockIdx.x * 8 + (threadIdx.x >> 5);
    const int lane = threadIdx.x & 31;
    const int head2 = warp & 31;
    const int tok = warp >> 5;
    const int pos = tok & (L_ - 1);

    float* x = proj + (size_t)tok * PW_ + (size_t)head2 * DH_;
    float v0 = x[lane];
    float v1 = x[lane + 32];
    float v2 = x[lane + 64];
    float v3 = x[lane + 96];

    float ss = v0 * v0 + v1 * v1 + v2 * v2 + v3 * v3;
#pragma unroll
    for (int o = 16; o; o >>= 1) ss += __shfl_xor_sync(FULLM, ss, o);
    const float r = rsqrtf(ss * (1.0f / DH_) + EPS_);
    v0 *= r; v1 *= r; v2 *= r; v3 *= r;

    const float kf = 9.210340371976184f / 64.0f;
    const float fpos = (float)pos;
    const float a0 = fpos * __expf(-kf * (float)lane);
    const float a1 = fpos * __expf(-kf * (float)(lane + 32));
    float c0, s0, c1, s1;
    sincosf(a0, &s0, &c0);
    sincosf(a1, &s1, &c1);

    x[lane]      = v0 * c0 - v2 * s0;
    x[lane + 64] = v0 * s0 + v2 * c0;
    x[lane + 32] = v1 * c1 - v3 * s1;
    x[lane + 96] = v1 * s1 + v3 * c1;
}

// ===========================================================================
extern "C" void kernel_launch(void* const* d_in, const int* in_sizes, int n_in,
                              void* d_out, int out_size)
{
    const float* hidden = (const float*)d_in[0];   // [B,L,HID]
    const float* Wqkvg  = (const float*)d_in[1];   // [HID, PW]
    const float* Wout   = (const float*)d_in[2];   // [HID, HID]
    float* out = (float*)d_out;                    // [B,L,HID]

    float* proj;
    __half *attnh, *hidh, *wqh, *woh;
    cudaGetSymbolAddress((void**)&proj,  g_proj);
    cudaGetSymbolAddress((void**)&attnh, g_attnh);
    cudaGetSymbolAddress((void**)&hidh,  g_hidh);
    cudaGetSymbolAddress((void**)&wqh,   g_wqh);
    cudaGetSymbolAddress((void**)&woh,   g_woh);

    cudaFuncSetAttribute(gemm_h,
                         cudaFuncAttributeMaxDynamicSharedMemorySize, GEMM_SMEM);
    cudaFuncSetAttribute(flash_h,
                         cudaFuncAttributeMaxDynamicSharedMemorySize, FLASH_SMEM);

    // 0) convert inputs to fp16
    {
        const int n4h = MTOK_ * HID_ / 4;
        cvt_f16_k<<<(n4h + 255) / 256, 256>>>((const float4*)hidden,
                                              (uint2*)hidh, n4h);
        const int n4q = HID_ * PW_ / 4;
        cvt_f16_k<<<(n4q + 255) / 256, 256>>>((const float4*)Wqkvg,
                                              (uint2*)wqh, n4q);
        const int n4o = HID_ * HID_ / 4;
        cvt_f16_k<<<(n4o + 255) / 256, 256>>>((const float4*)Wout,
                                              (uint2*)woh, n4o);
    }

    // 1) proj = hidden @ W_qkvg   (fp16 mma + ldmatrix, f32 accum)
    gemm_h<<<dim3(PW_ / BN, MTOK_ / BM), 128, GEMM_SMEM>>>(
        hidh, HID_, wqh, PW_, proj, PW_, HID_);

    // 2) RMSNorm + RoPE on q,k (f32, in place)
    norm_rope_kernel<<<(MTOK_ * 2 * H_) / 8, 256>>>(proj);

    // 3) fused flash attention + gate (fp16 mma; writes half attn)
    flash_h<<<dim3(L_ / 128, B_ * H_), 256, FLASH_SMEM>>>(proj, attnh);

    // 4) out = attn @ W_out
    gemm_h<<<dim3(HID_ / BN, MTOK_ / BM), 128, GEMM_SMEM>>>(
        attnh, HID_, woh, HID_, out, HID_, HID_);
}

// round 17
// speedup vs baseline: 2.1075x; 1.4302x over previous
#include <cuda_runtime.h>
#include <cuda_fp16.h>
#include <math.h>
#include <stdint.h>

#define B_    4
#define L_    2048
#define HID_  2048
#define H_    16
#define DH_   128
#define QKV_  (3 * HID_)          // 6144
#define PW_   (QKV_ + HID_)       // 8192
#define MTOK_ (B_ * L_)           // 8192
#define EPS_  1e-5f
#define SCALE_ 0.08838834764831845f   // 1/sqrt(128)
#define FULLM 0xffffffffu

// Scratch (allocation-free rule: __device__ globals)
__device__ float  g_proj[(size_t)MTOK_ * PW_];    // 256 MB (f32 proj output)
__device__ __half g_attnh[(size_t)MTOK_ * HID_];  // 32 MB
__device__ __half g_hidh[(size_t)MTOK_ * HID_];   // 32 MB
__device__ __half g_wqh[(size_t)HID_ * PW_];      // 32 MB
__device__ __half g_woh[(size_t)HID_ * HID_];     // 8 MB
__device__ __half g_qh[(size_t)MTOK_ * HID_];     // 32 MB compact [b,h,l,d]
__device__ __half g_kh[(size_t)MTOK_ * HID_];     // 32 MB
__device__ __half g_vh[(size_t)MTOK_ * HID_];     // 32 MB

__device__ __forceinline__ uint32_t h2u(__half2 h) {
    return *(uint32_t*)&h;
}

__device__ __forceinline__ void mma16(float* c, const uint32_t* a, const uint32_t* b) {
    asm volatile(
        "mma.sync.aligned.m16n8k16.row.col.f32.f16.f16.f32 "
        "{%0,%1,%2,%3}, {%4,%5,%6,%7}, {%8,%9}, {%0,%1,%2,%3};\n"
        : "+f"(c[0]), "+f"(c[1]), "+f"(c[2]), "+f"(c[3])
        : "r"(a[0]), "r"(a[1]), "r"(a[2]), "r"(a[3]), "r"(b[0]), "r"(b[1]));
}

__device__ __forceinline__ void ldsm4(uint32_t* r, uint32_t addr) {
    asm volatile(
        "ldmatrix.sync.aligned.m8n8.x4.shared.b16 {%0,%1,%2,%3}, [%4];"
        : "=r"(r[0]), "=r"(r[1]), "=r"(r[2]), "=r"(r[3]) : "r"(addr));
}

__device__ __forceinline__ void ldsm4t(uint32_t* r, uint32_t addr) {
    asm volatile(
        "ldmatrix.sync.aligned.m8n8.x4.trans.shared.b16 {%0,%1,%2,%3}, [%4];"
        : "=r"(r[0]), "=r"(r[1]), "=r"(r[2]), "=r"(r[3]) : "r"(addr));
}

__device__ __forceinline__ void cpa16(uint32_t dst, const void* src) {
    asm volatile("cp.async.ca.shared.global [%0], [%1], 16;\n"
                 :: "r"(dst), "l"(src));
}

// ===========================================================================
// f32 -> f16 convert
// ===========================================================================
__global__ __launch_bounds__(256) void cvt_f16_k(
    const float4* __restrict__ in, uint2* __restrict__ outp, int n4)
{
    const int i = blockIdx.x * 256 + threadIdx.x;
    if (i < n4) {
        float4 v = in[i];
        uint2 o;
        o.x = h2u(__floats2half2_rn(v.x, v.y));
        o.y = h2u(__floats2half2_rn(v.z, v.w));
        outp[i] = o;
    }
}

// ===========================================================================
// fp16 NN GEMM via ldmatrix + 3-stage cp.async.
// 128 thr/CTA, tile 128x128x32, warp tile 64x64, 2 CTA/SM.
// ===========================================================================
#define BM 128
#define BN 128
#define BK 32
#define ASTRu 20                     // u32 per A row
#define BSTRu 68                     // u32 per B row
#define A_STu (BM * ASTRu)           // 2560 u32
#define B_STu (BK * BSTRu)           // 2176 u32
#define STFu (A_STu + B_STu)         // 4736 u32
#define GEMM_SMEM (3 * STFu * 4)     // 56832 bytes

__global__ __launch_bounds__(128, 2) void gemm_h(
    const __half* __restrict__ A, int lda,
    const __half* __restrict__ B, int ldb,
    float* __restrict__ C, int ldc, int K)
{
    extern __shared__ uint32_t smu[];
    const int tid = threadIdx.x;
    const int m0 = blockIdx.y * BM, n0 = blockIdx.x * BN;
    const int warp = tid >> 5, lane = tid & 31;
    const int wm = (warp >> 1) * 64;
    const int wn = (warp & 1) * 64;
    const int lr = lane >> 2, lc = lane & 3;

    const uint32_t sb = (uint32_t)__cvta_generic_to_shared(smu);

    const uint32_t aoff = (uint32_t)((lane & 15) * (ASTRu * 4) + (lane >> 4) * 16);
    const uint32_t boff = (uint32_t)(((lane & 7) + ((lane >> 3) & 1) * 8) * (BSTRu * 4)
                                     + ((lane >> 4) * 8) * 2);

    const int br = tid >> 2, bq = tid & 3;

#define LOAD_STAGE(s, kt)                                                     \
    {                                                                         \
        const uint32_t ab = sb + ((s) * STFu + tid * ASTRu) * 4;              \
        const __half* ag = A + (size_t)(m0 + tid) * lda + (kt) * BK;          \
        _Pragma("unroll")                                                     \
        for (int c = 0; c < 4; c++) cpa16(ab + c * 16, ag + c * 8);           \
        const uint32_t bb = sb + ((s) * STFu + A_STu + br * BSTRu) * 4;       \
        const __half* bg = B + (size_t)((kt) * BK + br) * ldb + n0;           \
        _Pragma("unroll")                                                     \
        for (int c = 0; c < 4; c++)                                           \
            cpa16(bb + (c * 4 + bq) * 16, bg + (c * 4 + bq) * 8);             \
        asm volatile("cp.async.commit_group;\n" ::: "memory");                \
    }

    float acc[4][8][4];
#pragma unroll
    for (int mt = 0; mt < 4; mt++)
#pragma unroll
        for (int nt = 0; nt < 8; nt++)
#pragma unroll
            for (int e = 0; e < 4; e++) acc[mt][nt][e] = 0.f;

#define COMP(pp, ks)                                                         \
    {                                                                        \
        const uint32_t ab = sb + (pp) * (STFu * 4);                          \
        const uint32_t bb = ab + A_STu * 4;                                  \
        uint32_t af[4][4];                                                   \
        _Pragma("unroll")                                                    \
        for (int mt = 0; mt < 4; mt++)                                       \
            ldsm4(af[mt],                                                    \
                  ab + (wm + mt * 16) * (ASTRu * 4) + aoff + (ks) * 32);     \
        uint32_t bf[4][4];                                                   \
        _Pragma("unroll")                                                    \
        for (int nt2 = 0; nt2 < 4; nt2++)                                    \
            ldsm4t(bf[nt2],                                                  \
                   bb + (ks) * 16 * (BSTRu * 4) + boff                       \
                      + (wn + nt2 * 16) * 2);                                \
        _Pragma("unroll")                                                    \
        for (int mt = 0; mt < 4; mt++)                                       \
            _Pragma("unroll")                                                \
            for (int nt2 = 0; nt2 < 4; nt2++) {                              \
                mma16(acc[mt][2 * nt2], af[mt], &bf[nt2][0]);                \
                mma16(acc[mt][2 * nt2 + 1], af[mt], &bf[nt2][2]);            \
            }                                                                \
    }

    const int T = K >> 5;    // >= 2
    LOAD_STAGE(0, 0);
    LOAD_STAGE(1, 1);

    for (int t = 0; t < T; t++) {
        if (t + 1 < T) {
            asm volatile("cp.async.wait_group 1;\n" ::: "memory");
        } else {
            asm volatile("cp.async.wait_group 0;\n" ::: "memory");
        }
        __syncthreads();
        if (t + 2 < T) {
            int sn = t + 2;
            sn = sn - (sn / 3) * 3;
            LOAD_STAGE(sn, t + 2);
        }
        int s = t - (t / 3) * 3;
        COMP(s, 0);
        COMP(s, 1);
    }

#pragma unroll
    for (int mt = 0; mt < 4; mt++)
#pragma unroll
        for (int nt = 0; nt < 8; nt++) {
            const int r = m0 + wm + mt * 16 + lr;
            const int c = n0 + wn + nt * 8 + lc * 2;
            *(float2*)(C + (size_t)r * ldc + c) =
                make_float2(acc[mt][nt][0], acc[mt][nt][1]);
            *(float2*)(C + (size_t)(r + 8) * ldc + c) =
                make_float2(acc[mt][nt][2], acc[mt][nt][3]);
        }
#undef LOAD_STAGE
#undef COMP
}

// ===========================================================================
// RMSNorm + RoPE + f16 convert to compact per-head buffers.
// One warp per (tok, hh). hh 0..15 q (scaled), 16..31 k, 32..47 v (copy).
// Lane holds d = 4*lane .. 4*lane+3 (float4).
// ===========================================================================
__global__ __launch_bounds__(256) void norm_rope_kernel(
    const float* __restrict__ proj,
    __half* __restrict__ qh, __half* __restrict__ kh, __half* __restrict__ vh)
{
    const int warp = blockIdx.x * 8 + (threadIdx.x >> 5);
    const int lane = threadIdx.x & 31;
    const int hh = warp % 48;
    const int tok = warp / 48;
    const int pos = tok & (L_ - 1);
    const int b = tok >> 11;

    float4 v = *(const float4*)(proj + (size_t)tok * PW_ + (size_t)hh * DH_ + 4 * lane);

    if (hh >= 32) {
        const int head = hh - 32;
        uint2 o;
        o.x = h2u(__floats2half2_rn(v.x, v.y));
        o.y = h2u(__floats2half2_rn(v.z, v.w));
        *(uint2*)(vh + ((size_t)(b * H_ + head) * L_ + pos) * DH_ + 4 * lane) = o;
        return;
    }

    float ss = v.x * v.x + v.y * v.y + v.z * v.z + v.w * v.w;
#pragma unroll
    for (int o = 16; o; o >>= 1) ss += __shfl_xor_sync(FULLM, ss, o);
    const float r = rsqrtf(ss * (1.0f / DH_) + EPS_);
    v.x *= r; v.y *= r; v.z *= r; v.w *= r;

    // partner values across the 64-offset (lane ^ 16)
    const float p0 = __shfl_xor_sync(FULLM, v.x, 16);
    const float p1 = __shfl_xor_sync(FULLM, v.y, 16);
    const float p2 = __shfl_xor_sync(FULLM, v.z, 16);
    const float p3 = __shfl_xor_sync(FULLM, v.w, 16);

    const float kf = 9.210340371976184f / 64.0f;   // ln(10000)/64
    const float fpos = (float)pos;
    const int i0 = 4 * (lane & 15);
    float c[4], s[4];
#pragma unroll
    for (int j = 0; j < 4; j++) {
        const float a = fpos * __expf(-kf * (float)(i0 + j));
        sincosf(a, &s[j], &c[j]);
    }

    float o0, o1, o2, o3;
    if (lane < 16) {
        o0 = v.x * c[0] - p0 * s[0];
        o1 = v.y * c[1] - p1 * s[1];
        o2 = v.z * c[2] - p2 * s[2];
        o3 = v.w * c[3] - p3 * s[3];
    } else {
        o0 = p0 * s[0] + v.x * c[0];
        o1 = p1 * s[1] + v.y * c[1];
        o2 = p2 * s[2] + v.z * c[2];
        o3 = p3 * s[3] + v.w * c[3];
    }

    __half* dst;
    if (hh < 16) {
        o0 *= SCALE_; o1 *= SCALE_; o2 *= SCALE_; o3 *= SCALE_;
        dst = qh + ((size_t)(b * H_ + hh) * L_ + pos) * DH_ + 4 * lane;
    } else {
        dst = kh + ((size_t)(b * H_ + (hh - 16)) * L_ + pos) * DH_ + 4 * lane;
    }
    uint2 o;
    o.x = h2u(__floats2half2_rn(o0, o1));
    o.y = h2u(__floats2half2_rn(o2, o3));
    *(uint2*)dst = o;
}

// ===========================================================================
// Flash attention fp16 via ldmatrix (causal, online softmax) + sigmoid gate.
// Inputs: compact half qh/kh/vh (q pre-scaled). Gate read f32 from proj.
// Smem: Q/K [128 rows][128 halves] stride 68 u32; V [128 k][128 d] stride 68.
// ===========================================================================
#define FST 68
#define FSZ (128 * FST)                 // 8704 u32 per tile
#define FLASH_SMEM (3 * FSZ * 4)        // 104448 bytes

__global__ __launch_bounds__(256, 1) void flash_h(
    const __half* __restrict__ qh, const __half* __restrict__ kh,
    const __half* __restrict__ vh, const float* __restrict__ proj,
    __half* __restrict__ attnh)
{
    extern __shared__ uint32_t smu[];
    const uint32_t sb = (uint32_t)__cvta_generic_to_shared(smu);
    const uint32_t Kb = sb + FSZ * 4;
    const uint32_t Vb = sb + 2 * FSZ * 4;

    const int it = blockIdx.x, bh = blockIdx.y;
    const int b = bh >> 4, h = bh & 15;
    const size_t hb = (size_t)bh * L_ * DH_;
    const __half* Qp = qh + hb;
    const __half* Kp = kh + hb;
    const __half* Vp = vh + hb;
    const float* Gp = proj + (size_t)b * L_ * PW_ + QKV_ + (size_t)h * DH_;
    __half* Op = attnh + (size_t)b * L_ * HID_ + (size_t)h * DH_;

    const int tid = threadIdx.x, warp = tid >> 5, lane = tid & 31;
    const int lr = lane >> 2, lc = lane & 3;
    const int wm = warp * 16;
    const int i0 = it * 128;

    // --- load Q tile (uint4 copies) ---
#pragma unroll
    for (int i = 0; i < 8; i++) {
        const int task = tid + i * 256;
        const int row = task >> 4, ch = task & 15;
        uint4 u = *(const uint4*)(Qp + (size_t)(i0 + row) * DH_ + ch * 8);
        *(uint4*)(smu + row * FST + ch * 4) = u;
    }
    __syncthreads();

    // --- hoist Q fragments ---
    uint32_t qf[8][4];
    const uint32_t qoff = (uint32_t)((wm + (lane & 15)) * (FST * 4) + (lane >> 4) * 16);
#pragma unroll
    for (int ks = 0; ks < 8; ks++)
        ldsm4(qf[ks], sb + qoff + ks * 32);

    float m0v = -1e30f, m1v = -1e30f, l0 = 0.f, l1 = 0.f;
    float oacc[16][4];
#pragma unroll
    for (int nt = 0; nt < 16; nt++)
#pragma unroll
        for (int e = 0; e < 4; e++) oacc[nt][e] = 0.f;

    const int r0g = i0 + wm + lr, r1g = r0g + 8;
    const uint32_t koff = (uint32_t)((lane & 15) * (FST * 4) + (lane >> 4) * 16);
    const uint32_t voff = (uint32_t)(((lane & 7) + ((lane >> 3) & 1) * 8) * (FST * 4)
                                     + (lane >> 4) * 16);

    for (int jt = 0; jt <= it; ++jt) {
        const int j0 = jt * 128;
        // --- load K, V tiles ---
#pragma unroll
        for (int i = 0; i < 8; i++) {
            const int task = tid + i * 256;
            const int row = task >> 4, ch = task & 15;
            uint4 uk = *(const uint4*)(Kp + (size_t)(j0 + row) * DH_ + ch * 8);
            *(uint4*)(smu + FSZ + row * FST + ch * 4) = uk;
            uint4 uv = *(const uint4*)(Vp + (size_t)(j0 + row) * DH_ + ch * 8);
            *(uint4*)(smu + 2 * FSZ + row * FST + ch * 4) = uv;
        }
        __syncthreads();

        // --- S = Q @ K^T ---
        float sacc[16][4];
#pragma unroll
        for (int nt = 0; nt < 16; nt++)
#pragma unroll
            for (int e = 0; e < 4; e++) sacc[nt][e] = 0.f;

#pragma unroll
        for (int ks = 0; ks < 8; ks++) {
            uint32_t kbf[8][4];
#pragma unroll
            for (int g = 0; g < 8; g++)
                ldsm4(kbf[g], Kb + g * 16 * (FST * 4) + koff + ks * 32);
#pragma unroll
            for (int nt = 0; nt < 16; nt++) {
                uint32_t bf[2];
                bf[0] = kbf[nt >> 1][nt & 1];
                bf[1] = kbf[nt >> 1][(nt & 1) + 2];
                mma16(sacc[nt], qf[ks], bf);
            }
        }

        // causal mask on the diagonal tile
        if (jt == it) {
#pragma unroll
            for (int nt = 0; nt < 16; nt++) {
                const int c0 = j0 + nt * 8 + 2 * lc;
                if (c0 > r0g)     sacc[nt][0] = -1e30f;
                if (c0 + 1 > r0g) sacc[nt][1] = -1e30f;
                if (c0 > r1g)     sacc[nt][2] = -1e30f;
                if (c0 + 1 > r1g) sacc[nt][3] = -1e30f;
            }
        }

        // online softmax stats (quad reduce)
        float tm0 = -1e30f, tm1 = -1e30f;
#pragma unroll
        for (int nt = 0; nt < 16; nt++) {
            tm0 = fmaxf(tm0, fmaxf(sacc[nt][0], sacc[nt][1]));
            tm1 = fmaxf(tm1, fmaxf(sacc[nt][2], sacc[nt][3]));
        }
        tm0 = fmaxf(tm0, __shfl_xor_sync(FULLM, tm0, 1));
        tm0 = fmaxf(tm0, __shfl_xor_sync(FULLM, tm0, 2));
        tm1 = fmaxf(tm1, __shfl_xor_sync(FULLM, tm1, 1));
        tm1 = fmaxf(tm1, __shfl_xor_sync(FULLM, tm1, 2));

        const float mn0 = fmaxf(m0v, tm0), mn1 = fmaxf(m1v, tm1);
        const float sc0 = __expf(m0v - mn0), sc1 = __expf(m1v - mn1);
        m0v = mn0; m1v = mn1;

        uint32_t pk[16][2];
        float rs0 = 0.f, rs1 = 0.f;
#pragma unroll
        for (int nt = 0; nt < 16; nt++) {
            float p0 = __expf(sacc[nt][0] - mn0);
            float p1 = __expf(sacc[nt][1] - mn0);
            float p2 = __expf(sacc[nt][2] - mn1);
            float p3 = __expf(sacc[nt][3] - mn1);
            rs0 += p0 + p1; rs1 += p2 + p3;
            pk[nt][0] = h2u(__floats2half2_rn(p0, p1));
            pk[nt][1] = h2u(__floats2half2_rn(p2, p3));
            oacc[nt][0] *= sc0; oacc[nt][1] *= sc0;
            oacc[nt][2] *= sc1; oacc[nt][3] *= sc1;
        }
        rs0 += __shfl_xor_sync(FULLM, rs0, 1);
        rs0 += __shfl_xor_sync(FULLM, rs0, 2);
        rs1 += __shfl_xor_sync(FULLM, rs1, 1);
        rs1 += __shfl_xor_sync(FULLM, rs1, 2);
        l0 = l0 * sc0 + rs0;
        l1 = l1 * sc1 + rs1;

        // --- O += P @ V ---
#pragma unroll
        for (int ks = 0; ks < 8; ks++) {
            uint32_t a[4];
            a[0] = pk[2 * ks][0];
            a[1] = pk[2 * ks][1];
            a[2] = pk[2 * ks + 1][0];
            a[3] = pk[2 * ks + 1][1];
            uint32_t vbf[8][4];
#pragma unroll
            for (int g = 0; g < 8; g++)
                ldsm4t(vbf[g], Vb + ks * 16 * (FST * 4) + voff + g * 32);
#pragma unroll
            for (int nt = 0; nt < 16; nt++) {
                uint32_t bf[2];
                bf[0] = vbf[nt >> 1][2 * (nt & 1)];
                bf[1] = vbf[nt >> 1][2 * (nt & 1) + 1];
                mma16(oacc[nt], a, bf);
            }
        }
        __syncthreads();
    }

    // epilogue: normalize, sigmoid gate, store half
    const float inv0 = 1.f / l0, inv1 = 1.f / l1;
#pragma unroll
    for (int nt = 0; nt < 16; nt++) {
        const int c = nt * 8 + 2 * lc;
        const float2 g0 = *(const float2*)(Gp + (size_t)r0g * PW_ + c);
        const float2 g1 = *(const float2*)(Gp + (size_t)r1g * PW_ + c);
        float o0 = oacc[nt][0] * inv0 * (1.f / (1.f + __expf(-g0.x)));
        float o1 = oacc[nt][1] * inv0 * (1.f / (1.f + __expf(-g0.y)));
        float o2 = oacc[nt][2] * inv1 * (1.f / (1.f + __expf(-g1.x)));
        float o3 = oacc[nt][3] * inv1 * (1.f / (1.f + __expf(-g1.y)));
        *(uint32_t*)(Op + (size_t)r0g * HID_ + c) = h2u(__floats2half2_rn(o0, o1));
        *(uint32_t*)(Op + (size_t)r1g * HID_ + c) = h2u(__floats2half2_rn(o2, o3));
    }
}

// ===========================================================================
extern "C" void kernel_launch(void* const* d_in, const int* in_sizes, int n_in,
                              void* d_out, int out_size)
{
    const float* hidden = (const float*)d_in[0];   // [B,L,HID]
    const float* Wqkvg  = (const float*)d_in[1];   // [HID, PW]
    const float* Wout   = (const float*)d_in[2];   // [HID, HID]
    float* out = (float*)d_out;                    // [B,L,HID]

    float* proj;
    __half *attnh, *hidh, *wqh, *woh, *qh, *kh, *vh;
    cudaGetSymbolAddress((void**)&proj,  g_proj);
    cudaGetSymbolAddress((void**)&attnh, g_attnh);
    cudaGetSymbolAddress((void**)&hidh,  g_hidh);
    cudaGetSymbolAddress((void**)&wqh,   g_wqh);
    cudaGetSymbolAddress((void**)&woh,   g_woh);
    cudaGetSymbolAddress((void**)&qh,    g_qh);
    cudaGetSymbolAddress((void**)&kh,    g_kh);
    cudaGetSymbolAddress((void**)&vh,    g_vh);

    cudaFuncSetAttribute(gemm_h,
                         cudaFuncAttributeMaxDynamicSharedMemorySize, GEMM_SMEM);
    cudaFuncSetAttribute(flash_h,
                         cudaFuncAttributeMaxDynamicSharedMemorySize, FLASH_SMEM);

    // 0) convert inputs to fp16
    {
        const int n4h = MTOK_ * HID_ / 4;
        cvt_f16_k<<<(n4h + 255) / 256, 256>>>((const float4*)hidden,
                                              (uint2*)hidh, n4h);
        const int n4q = HID_ * PW_ / 4;
        cvt_f16_k<<<(n4q + 255) / 256, 256>>>((const float4*)Wqkvg,
                                              (uint2*)wqh, n4q);
        const int n4o = HID_ * HID_ / 4;
        cvt_f16_k<<<(n4o + 255) / 256, 256>>>((const float4*)Wout,
                                              (uint2*)woh, n4o);
    }

    // 1) proj = hidden @ W_qkvg   (fp16 mma + ldmatrix + cp.async)
    gemm_h<<<dim3(PW_ / BN, MTOK_ / BM), 128, GEMM_SMEM>>>(
        hidh, HID_, wqh, PW_, proj, PW_, HID_);

    // 2) RMSNorm + RoPE -> compact half qh/kh/vh (q pre-scaled)
    norm_rope_kernel<<<(MTOK_ * 48) / 8, 256>>>(proj, qh, kh, vh);

    // 3) fused flash attention + gate (ldmatrix; writes half attn)
    flash_h<<<dim3(L_ / 128, B_ * H_), 256, FLASH_SMEM>>>(
        qh, kh, vh, proj, attnh);

    // 4) out = attn @ W_out
    gemm_h<<<dim3(HID_ / BN, MTOK_ / BM), 128, GEMM_SMEM>>>(
        attnh, HID_, woh, HID_, out, HID_, HID_);
}